// round 16
// baseline (speedup 1.0000x reference)
#include <cuda_runtime.h>
#include <cuda_fp16.h>
#include <cstdint>

// ===========================================================================
// GaussProjDrop R16: R15 + smem-staged epilogue stores (full-sector uint4 STG).
//   out_g = (xg @ U)/3 + xg  (fp16), final kernel = pure permutation.
// ===========================================================================

namespace {
constexpr int M = 8 * 2048;   // 16384
constexpr int C = 1024;
constexpr float RAND_SCALE = 1.0f / 3.0f;

constexpr int BM = 128, BN = 128, BK = 64;
constexpr int NKT = C / BK;                  // 16
constexpr int STAGES = 3;
constexpr int A_SM_BYTES = BM * BK * 2;      // 16384
constexpr int B_SM_BYTES = BK * BN * 2;      // 16384
constexpr int STAGE_BYTES = A_SM_BYTES + B_SM_BYTES;   // 32768
constexpr int GSMEM = STAGES * STAGE_BYTES;            // 98304 -> 2 CTA/SM

constexpr int OUT_OFF   = 2 * STAGE_BYTES;   // staging buffer (stage 2, free in epilogue)
constexpr int OUT_PITCH = 272;               // 256B row + 16B pad (bank-spread)

constexpr int GATHER_BLOCKS = M / 8;                // 2048 (8 rows, 512 thr)
constexpr int UCONV_BLOCKS  = (C * C) / (512 * 4);  // 512
}

// Scratch (__device__ globals: allocation-free rule)
__device__ __half g_xg[(size_t)M * C];   // gathered x, fp16    (32 MB)
__device__ __half g_uh[(size_t)C * C];   // U, fp16               (2 MB)
__device__ __half g_og[(size_t)M * C];   // out_g fp16           (32 MB)

// ---------------------------------------------------------------------------
__device__ __forceinline__ void cp_async16(uint32_t dst, const void* src) {
    asm volatile("cp.async.cg.shared.global [%0], [%1], 16;" :: "r"(dst), "l"(src));
}
__device__ __forceinline__ uint32_t smem_u32(const void* p) {
    uint32_t a;
    asm("{ .reg .u64 t; cvta.to.shared.u64 t, %1; cvt.u32.u64 %0, t; }" : "=r"(a) : "l"(p));
    return a;
}
__device__ __forceinline__ void ldsm_x4(uint32_t r[4], uint32_t addr) {
    asm volatile("ldmatrix.sync.aligned.m8n8.x4.shared.b16 {%0,%1,%2,%3}, [%4];"
                 : "=r"(r[0]), "=r"(r[1]), "=r"(r[2]), "=r"(r[3]) : "r"(addr));
}
__device__ __forceinline__ void ldsm_x4_t(uint32_t r[4], uint32_t addr) {
    asm volatile("ldmatrix.sync.aligned.m8n8.x4.trans.shared.b16 {%0,%1,%2,%3}, [%4];"
                 : "=r"(r[0]), "=r"(r[1]), "=r"(r[2]), "=r"(r[3]) : "r"(addr));
}
__device__ __forceinline__ void mma_f16(float c[4], const uint32_t a[4], uint32_t b0, uint32_t b1) {
    asm volatile(
        "mma.sync.aligned.m16n8k16.row.col.f32.f16.f16.f32 "
        "{%0,%1,%2,%3}, {%4,%5,%6,%7}, {%8,%9}, {%0,%1,%2,%3};"
        : "+f"(c[0]), "+f"(c[1]), "+f"(c[2]), "+f"(c[3])
        : "r"(a[0]), "r"(a[1]), "r"(a[2]), "r"(a[3]), "r"(b0), "r"(b1));
}

// ---------------------------------------------------------------------------
// Launch 1 (merged): gather (512 thr, 8 rows, 2-stage cp.async) + uconv.
// ---------------------------------------------------------------------------
__global__ void __launch_bounds__(512)
gather_uconv_kernel(const float* __restrict__ x,
                    const float* __restrict__ U,
                    const int*   __restrict__ perm,
                    const int*   __restrict__ randint) {
    const int tid = threadIdx.x;

    if (blockIdx.x >= GATHER_BLOCKS) {
        int i = ((blockIdx.x - GATHER_BLOCKS) * 512 + tid) * 4;
        float4 v = *reinterpret_cast<const float4*>(U + i);
        *reinterpret_cast<__half2*>(g_uh + i)     = __floats2half2_rn(v.x, v.y);
        *reinterpret_cast<__half2*>(g_uh + i + 2) = __floats2half2_rn(v.z, v.w);
        return;
    }

    __shared__ float sx[8][C];                // 32 KB, two 4-row stages
    const int r0 = blockIdx.x * 8;
    const unsigned mult = ((unsigned)randint[0] * 6u) & 1023u;
    const uint32_t sxb = smem_u32(sx);

    #pragma unroll
    for (int s = 0; s < 2; s++) {
        #pragma unroll
        for (int i = 0; i < 2; i++) {
            int id = tid + i * 512;
            int rr = id >> 8, c4 = (id & 255) * 4;
            int row = s * 4 + rr;
            cp_async16(sxb + (row * C + c4) * 4,
                       x + (size_t)(r0 + row) * C + c4);
        }
        asm volatile("cp.async.commit_group;" ::: "memory");
    }

    asm volatile("cp.async.wait_group 1;" ::: "memory");
    __syncthreads();
    #pragma unroll
    for (int i = 0; i < 4; i++) {
        int id = tid + i * 512;
        int rr = id >> 9, j = (id & 511) * 2;
        unsigned m = (mult * (unsigned)(r0 + rr) + 1u) & 1023u;
        unsigned a0 = ((unsigned)perm[j]     * m) & 1023u;
        unsigned a1 = ((unsigned)perm[j + 1] * m) & 1023u;
        __half2 h = __floats2half2_rn(sx[rr][a0], sx[rr][a1]);
        *reinterpret_cast<__half2*>(g_xg + (size_t)(r0 + rr) * C + j) = h;
    }

    asm volatile("cp.async.wait_group 0;" ::: "memory");
    __syncthreads();
    #pragma unroll
    for (int i = 0; i < 4; i++) {
        int id = tid + i * 512;
        int rr = (id >> 9) + 4, j = (id & 511) * 2;
        unsigned m = (mult * (unsigned)(r0 + rr) + 1u) & 1023u;
        unsigned a0 = ((unsigned)perm[j]     * m) & 1023u;
        unsigned a1 = ((unsigned)perm[j + 1] * m) & 1023u;
        __half2 h = __floats2half2_rn(sx[rr][a0], sx[rr][a1]);
        *reinterpret_cast<__half2*>(g_xg + (size_t)(r0 + rr) * C + j) = h;
    }
}

// ---------------------------------------------------------------------------
// Launch 2: out_g = (xg @ U)/3 + xg, fp16.  R7 mainloop; staged epilogue.
// CTA 128x128x64, 256 thr, warps 2(m)x4(n), warp tile 64x32. 2 CTA/SM.
// ---------------------------------------------------------------------------
__device__ __forceinline__ void fill_stage(int f, int tid, uint32_t smb, int by, int bx) {
    const int s = f % STAGES;
    const uint32_t a_base = smb + s * STAGE_BYTES;
    const uint32_t b_base = a_base + A_SM_BYTES;
    const __half* Ag = g_xg + (size_t)(by * BM) * C + f * BK;
    const __half* Bg = g_uh + (size_t)(f * BK) * C + bx * BN;
    #pragma unroll
    for (int i = 0; i < 4; i++) {
        int id = tid + i * 256;
        int r = id >> 3, c = id & 7;
        cp_async16(a_base + r * 128 + ((c ^ (r & 7)) << 4), Ag + (size_t)r * C + c * 8);
    }
    #pragma unroll
    for (int i = 0; i < 4; i++) {
        int id = tid + i * 256;
        int r = id >> 4, c = id & 15;
        cp_async16(b_base + r * 256 + ((c ^ (r & 7)) << 4), Bg + (size_t)r * C + c * 8);
    }
    asm volatile("cp.async.commit_group;" ::: "memory");
}

__global__ void __launch_bounds__(256, 2)
gemm_kernel() {
    extern __shared__ char smem[];
    const uint32_t smb = smem_u32(smem);

    const int bx  = blockIdx.x;       // 0..7
    const int by  = blockIdx.y;       // 0..127
    const int tid = threadIdx.x;
    const int wid = tid >> 5, lane = tid & 31;
    const int wm  = wid & 1;
    const int wn  = wid >> 1;
    const int l7   = lane & 7;
    const int seg1 = (lane >> 3) & 1;
    const int seg2 = lane >> 4;

    float acc[4][4][4];
    #pragma unroll
    for (int i = 0; i < 4; i++)
        #pragma unroll
        for (int j = 0; j < 4; j++)
            #pragma unroll
            for (int q = 0; q < 4; q++) acc[i][j][q] = 0.f;

    #pragma unroll
    for (int f = 0; f < STAGES - 1; f++) fill_stage(f, tid, smb, by, bx);

    const int a_rowloc = wm * 64 + l7 + seg1 * 8;
    const int b_kloc   = l7 + seg1 * 8;
    const int b_ccbase = wn * 4 + seg2;

    for (int kt = 0; kt < NKT; kt++) {
        asm volatile("cp.async.wait_group %0;" :: "n"(STAGES - 2) : "memory");
        __syncthreads();

        const int f = kt + STAGES - 1;
        if (f < NKT) fill_stage(f, tid, smb, by, bx);

        const int s = kt % STAGES;
        const uint32_t As = smb + s * STAGE_BYTES;
        const uint32_t Bs = As + A_SM_BYTES;

        #pragma unroll
        for (int ks = 0; ks < 4; ks++) {
            uint32_t afr[4][4], bfr[2][4];
            const int a_chunk = 2 * ks + seg2;
            #pragma unroll
            for (int mt = 0; mt < 4; mt++)
                ldsm_x4(afr[mt], As + (a_rowloc + mt * 16) * 128 + ((a_chunk ^ l7) << 4));
            const int bk = ks * 16 + b_kloc;
            #pragma unroll
            for (int nb = 0; nb < 2; nb++)
                ldsm_x4_t(bfr[nb], Bs + bk * 256 + (((b_ccbase + nb * 2) ^ l7) << 4));
            #pragma unroll
            for (int mt = 0; mt < 4; mt++)
                #pragma unroll
                for (int nt = 0; nt < 4; nt++)
                    mma_f16(acc[mt][nt], afr[mt],
                            bfr[nt >> 1][2 * (nt & 1)], bfr[nt >> 1][2 * (nt & 1) + 1]);
        }
    }

    // ---- Fused epilogue: reload this CTA's A k-tiles (f = 2bx, 2bx+1) ----
    __syncthreads();                          // all MMA smem reads done
    #pragma unroll
    for (int t = 0; t < 2; t++) {
        const int f = 2 * bx + t;
        const uint32_t a_base = smb + t * STAGE_BYTES;
        const __half* Ag = g_xg + (size_t)(by * BM) * C + f * BK;
        #pragma unroll
        for (int i = 0; i < 4; i++) {
            int id = tid + i * 256;
            int r = id >> 3, c = id & 7;
            cp_async16(a_base + r * 128 + ((c ^ (r & 7)) << 4), Ag + (size_t)r * C + c * 8);
        }
    }
    asm volatile("cp.async.commit_group;" ::: "memory");
    asm volatile("cp.async.wait_group 0;" ::: "memory");
    __syncthreads();

    // out_g = acc/3 + xg, staged through smem for full-sector uint4 stores.
    // Pass p handles rows [p*64, p*64+64): warps with wm==p stage fused halves,
    // then ALL threads drain the staged rows with coalesced 16B stores.
    const int qid = lane >> 2, tq = lane & 3;
    #pragma unroll
    for (int p = 0; p < 2; p++) {
        if (wm == p) {
            #pragma unroll
            for (int mt = 0; mt < 4; mt++) {
                #pragma unroll
                for (int nt = 0; nt < 4; nt++) {
                    const int c   = wn * 32 + nt * 8 + 2 * tq;  // local col
                    const int t   = c >> 6;
                    const int kc  = c & 63;
                    const int chv = kc >> 3;
                    const int wb  = (kc & 7) * 2;
                    #pragma unroll
                    for (int h = 0; h < 2; h++) {
                        const int rl  = wm * 64 + mt * 16 + qid + h * 8; // 0..127
                        const int rlo = mt * 16 + qid + h * 8;           // 0..63
                        const char* pa = smem + t * STAGE_BYTES + rl * 128
                                       + ((chv ^ (rl & 7)) << 4) + wb;
                        float2 xv = __half22float2(*reinterpret_cast<const __half2*>(pa));
                        float ox = fmaf(acc[mt][nt][2 * h],     RAND_SCALE, xv.x);
                        float oy = fmaf(acc[mt][nt][2 * h + 1], RAND_SCALE, xv.y);
                        *reinterpret_cast<__half2*>(smem + OUT_OFF + rlo * OUT_PITCH + c * 2) =
                            __floats2half2_rn(ox, oy);
                    }
                }
            }
        }
        __syncthreads();
        // Drain: 64 rows x 16 uint4 chunks = 1024; 256 thr x 4
        #pragma unroll
        for (int i = 0; i < 4; i++) {
            int id = tid + i * 256;
            int r  = id >> 4, ch = id & 15;
            uint4 v = *reinterpret_cast<const uint4*>(smem + OUT_OFF + r * OUT_PITCH + ch * 16);
            *reinterpret_cast<uint4*>(
                g_og + (size_t)(by * BM + p * 64 + r) * C + bx * BN + ch * 8) = v;
        }
        __syncthreads();
    }
}

// ---------------------------------------------------------------------------
// Launch 3: pure permutation.  out[r][a(i)] = float(out_g[r][i])
// 8 rows per 512-thread block; uint4 fp16 reads; 96 MB total traffic.
// ---------------------------------------------------------------------------
__global__ void __launch_bounds__(512)
permute_kernel(const int* __restrict__ perm,
               const int* __restrict__ randint,
               float*     __restrict__ out) {
    __shared__ float so[8][C];
    const int r0 = blockIdx.x * 8;
    const unsigned mult = ((unsigned)randint[0] * 6u) & 1023u;
    const int tid = threadIdx.x;

    #pragma unroll
    for (int i = 0; i < 2; i++) {
        int id = tid + i * 512;                  // 0..1023 uint4 chunks
        int rr = id >> 7, j = (id & 127) * 8;
        unsigned m = (mult * (unsigned)(r0 + rr) + 1u) & 1023u;
        uint4 raw = *reinterpret_cast<const uint4*>(g_og + (size_t)(r0 + rr) * C + j);
        const uint32_t w[4] = {raw.x, raw.y, raw.z, raw.w};
        #pragma unroll
        for (int q = 0; q < 4; q++) {
            float2 v = __half22float2(*reinterpret_cast<const __half2*>(&w[q]));
            so[rr][((unsigned)perm[j + 2 * q]     * m) & 1023u] = v.x;
            so[rr][((unsigned)perm[j + 2 * q + 1] * m) & 1023u] = v.y;
        }
    }
    __syncthreads();

    #pragma unroll
    for (int i = 0; i < 4; i++) {
        int id = tid + i * 512;
        int rr = id >> 8, j = (id & 255) * 4;
        *reinterpret_cast<float4*>(out + (size_t)(r0 + rr) * C + j) =
            *reinterpret_cast<const float4*>(&so[rr][j]);
    }
}

// ---------------------------------------------------------------------------
extern "C" void kernel_launch(void* const* d_in, const int* in_sizes, int n_in,
                              void* d_out, int out_size) {
    const float* x       = (const float*)d_in[0];
    const float* U       = (const float*)d_in[1];
    const int*   perm    = (const int*)d_in[2];
    const int*   randint = (const int*)d_in[3];
    float*       out     = (float*)d_out;

    static bool attr_done = false;
    if (!attr_done) {
        cudaFuncSetAttribute(gemm_kernel,
                             cudaFuncAttributeMaxDynamicSharedMemorySize, GSMEM);
        attr_done = true;
    }

    gather_uconv_kernel<<<GATHER_BLOCKS + UCONV_BLOCKS, 512>>>(x, U, perm, randint);
    gemm_kernel<<<dim3(C / BN, M / BM), 256, GSMEM>>>();
    permute_kernel<<<M / 8, 512>>>(perm, randint, out);
}

// round 17
// speedup vs baseline: 1.0400x; 1.0400x over previous
#include <cuda_runtime.h>
#include <cuda_fp16.h>
#include <cstdint>

// ===========================================================================
// GaussProjDrop R17: R14 (best, 129.8us) with a 4-stage gather pipeline.
//   out_g = (xg @ U)/3 + xg  (fp32, computed in GEMM epilogue)
//   final kernel: pure permutation out[r][a(i)] = out_g[r][i]
// ===========================================================================

namespace {
constexpr int M = 8 * 2048;   // 16384
constexpr int C = 1024;
constexpr float RAND_SCALE = 1.0f / 3.0f;

constexpr int BM = 128, BN = 128, BK = 64;
constexpr int NKT = C / BK;                  // 16
constexpr int STAGES = 3;
constexpr int A_SM_BYTES = BM * BK * 2;      // 16384
constexpr int B_SM_BYTES = BK * BN * 2;      // 16384
constexpr int STAGE_BYTES = A_SM_BYTES + B_SM_BYTES;   // 32768
constexpr int GSMEM = STAGES * STAGE_BYTES;            // 98304 -> 2 CTA/SM

constexpr int GATHER_BLOCKS = M / 8;                // 2048 (8 rows, 512 thr)
constexpr int UCONV_BLOCKS  = (C * C) / (512 * 4);  // 512
}

// Scratch (__device__ globals: allocation-free rule)
__device__ __half g_xg[(size_t)M * C];   // gathered x, fp16   (32 MB)
__device__ __half g_uh[(size_t)C * C];   // U, fp16              (2 MB)
__device__ float  g_og[(size_t)M * C];   // out_g = xg@U/3 + xg (64 MB)

// ---------------------------------------------------------------------------
__device__ __forceinline__ void cp_async16(uint32_t dst, const void* src) {
    asm volatile("cp.async.cg.shared.global [%0], [%1], 16;" :: "r"(dst), "l"(src));
}
__device__ __forceinline__ uint32_t smem_u32(const void* p) {
    uint32_t a;
    asm("{ .reg .u64 t; cvta.to.shared.u64 t, %1; cvt.u32.u64 %0, t; }" : "=r"(a) : "l"(p));
    return a;
}
__device__ __forceinline__ void ldsm_x4(uint32_t r[4], uint32_t addr) {
    asm volatile("ldmatrix.sync.aligned.m8n8.x4.shared.b16 {%0,%1,%2,%3}, [%4];"
                 : "=r"(r[0]), "=r"(r[1]), "=r"(r[2]), "=r"(r[3]) : "r"(addr));
}
__device__ __forceinline__ void ldsm_x4_t(uint32_t r[4], uint32_t addr) {
    asm volatile("ldmatrix.sync.aligned.m8n8.x4.trans.shared.b16 {%0,%1,%2,%3}, [%4];"
                 : "=r"(r[0]), "=r"(r[1]), "=r"(r[2]), "=r"(r[3]) : "r"(addr));
}
__device__ __forceinline__ void mma_f16(float c[4], const uint32_t a[4], uint32_t b0, uint32_t b1) {
    asm volatile(
        "mma.sync.aligned.m16n8k16.row.col.f32.f16.f16.f32 "
        "{%0,%1,%2,%3}, {%4,%5,%6,%7}, {%8,%9}, {%0,%1,%2,%3};"
        : "+f"(c[0]), "+f"(c[1]), "+f"(c[2]), "+f"(c[3])
        : "r"(a[0]), "r"(a[1]), "r"(a[2]), "r"(a[3]), "r"(b0), "r"(b1));
}

// ---------------------------------------------------------------------------
// Launch 1 (merged): gather (512 thr, 8 rows, 4x2-row cp.async stages) + uconv.
// ---------------------------------------------------------------------------
__global__ void __launch_bounds__(512)
gather_uconv_kernel(const float* __restrict__ x,
                    const float* __restrict__ U,
                    const int*   __restrict__ perm,
                    const int*   __restrict__ randint) {
    const int tid = threadIdx.x;

    if (blockIdx.x >= GATHER_BLOCKS) {
        int i = ((blockIdx.x - GATHER_BLOCKS) * 512 + tid) * 4;
        float4 v = *reinterpret_cast<const float4*>(U + i);
        *reinterpret_cast<__half2*>(g_uh + i)     = __floats2half2_rn(v.x, v.y);
        *reinterpret_cast<__half2*>(g_uh + i + 2) = __floats2half2_rn(v.z, v.w);
        return;
    }

    __shared__ float sx[8][C];                // 32 KB; 4 stages x 2 rows
    const int r0 = blockIdx.x * 8;
    const unsigned mult = ((unsigned)randint[0] * 6u) & 1023u;
    const uint32_t sxb = smem_u32(sx);

    // Issue all 4 stages' loads up front (stage = 2 rows = 512 16B chunks)
    #pragma unroll
    for (int s = 0; s < 4; s++) {
        int rr = tid >> 8, c4 = (tid & 255) * 4;   // one chunk per thread
        int row = s * 2 + rr;
        cp_async16(sxb + (row * C + c4) * 4, x + (size_t)(r0 + row) * C + c4);
        asm volatile("cp.async.commit_group;" ::: "memory");
    }

    // Drain stages: permute 2 rows while later stages' loads are in flight.
    #pragma unroll
    for (int s = 0; s < 4; s++) {
        if (s == 0)      asm volatile("cp.async.wait_group 3;" ::: "memory");
        else if (s == 1) asm volatile("cp.async.wait_group 2;" ::: "memory");
        else if (s == 2) asm volatile("cp.async.wait_group 1;" ::: "memory");
        else             asm volatile("cp.async.wait_group 0;" ::: "memory");
        __syncthreads();
        #pragma unroll
        for (int i = 0; i < 2; i++) {
            int id = tid + i * 512;               // 0..1023 half2 (2 rows)
            int rr = s * 2 + (id >> 9), j = (id & 511) * 2;
            unsigned m = (mult * (unsigned)(r0 + rr) + 1u) & 1023u;
            unsigned a0 = ((unsigned)perm[j]     * m) & 1023u;
            unsigned a1 = ((unsigned)perm[j + 1] * m) & 1023u;
            __half2 h = __floats2half2_rn(sx[rr][a0], sx[rr][a1]);
            *reinterpret_cast<__half2*>(g_xg + (size_t)(r0 + rr) * C + j) = h;
        }
    }
}

// ---------------------------------------------------------------------------
// Launch 2: out_g = (xg @ U)/3 + xg.  R7 mainloop; fused fp32 epilogue (R14).
// CTA 128x128x64, 256 thr, warps 2(m)x4(n), warp tile 64x32. 2 CTA/SM.
// ---------------------------------------------------------------------------
__device__ __forceinline__ void fill_stage(int f, int tid, uint32_t smb, int by, int bx) {
    const int s = f % STAGES;
    const uint32_t a_base = smb + s * STAGE_BYTES;
    const uint32_t b_base = a_base + A_SM_BYTES;
    const __half* Ag = g_xg + (size_t)(by * BM) * C + f * BK;
    const __half* Bg = g_uh + (size_t)(f * BK) * C + bx * BN;
    #pragma unroll
    for (int i = 0; i < 4; i++) {
        int id = tid + i * 256;
        int r = id >> 3, c = id & 7;
        cp_async16(a_base + r * 128 + ((c ^ (r & 7)) << 4), Ag + (size_t)r * C + c * 8);
    }
    #pragma unroll
    for (int i = 0; i < 4; i++) {
        int id = tid + i * 256;
        int r = id >> 4, c = id & 15;
        cp_async16(b_base + r * 256 + ((c ^ (r & 7)) << 4), Bg + (size_t)r * C + c * 8);
    }
    asm volatile("cp.async.commit_group;" ::: "memory");
}

__global__ void __launch_bounds__(256, 2)
gemm_kernel() {
    extern __shared__ char smem[];
    const uint32_t smb = smem_u32(smem);

    const int bx  = blockIdx.x;       // 0..7
    const int by  = blockIdx.y;       // 0..127
    const int tid = threadIdx.x;
    const int wid = tid >> 5, lane = tid & 31;
    const int wm  = wid & 1;
    const int wn  = wid >> 1;
    const int l7   = lane & 7;
    const int seg1 = (lane >> 3) & 1;
    const int seg2 = lane >> 4;

    float acc[4][4][4];
    #pragma unroll
    for (int i = 0; i < 4; i++)
        #pragma unroll
        for (int j = 0; j < 4; j++)
            #pragma unroll
            for (int q = 0; q < 4; q++) acc[i][j][q] = 0.f;

    #pragma unroll
    for (int f = 0; f < STAGES - 1; f++) fill_stage(f, tid, smb, by, bx);

    const int a_rowloc = wm * 64 + l7 + seg1 * 8;
    const int b_kloc   = l7 + seg1 * 8;
    const int b_ccbase = wn * 4 + seg2;

    for (int kt = 0; kt < NKT; kt++) {
        asm volatile("cp.async.wait_group %0;" :: "n"(STAGES - 2) : "memory");
        __syncthreads();

        const int f = kt + STAGES - 1;
        if (f < NKT) fill_stage(f, tid, smb, by, bx);

        const int s = kt % STAGES;
        const uint32_t As = smb + s * STAGE_BYTES;
        const uint32_t Bs = As + A_SM_BYTES;

        #pragma unroll
        for (int ks = 0; ks < 4; ks++) {
            uint32_t afr[4][4], bfr[2][4];
            const int a_chunk = 2 * ks + seg2;
            #pragma unroll
            for (int mt = 0; mt < 4; mt++)
                ldsm_x4(afr[mt], As + (a_rowloc + mt * 16) * 128 + ((a_chunk ^ l7) << 4));
            const int bk = ks * 16 + b_kloc;
            #pragma unroll
            for (int nb = 0; nb < 2; nb++)
                ldsm_x4_t(bfr[nb], Bs + bk * 256 + (((b_ccbase + nb * 2) ^ l7) << 4));
            #pragma unroll
            for (int mt = 0; mt < 4; mt++)
                #pragma unroll
                for (int nt = 0; nt < 4; nt++)
                    mma_f16(acc[mt][nt], afr[mt],
                            bfr[nt >> 1][2 * (nt & 1)], bfr[nt >> 1][2 * (nt & 1) + 1]);
        }
    }

    // ---- Fused epilogue: reload this CTA's A k-tiles (f = 2bx, 2bx+1) ----
    __syncthreads();                          // all MMA smem reads done
    #pragma unroll
    for (int t = 0; t < 2; t++) {
        const int f = 2 * bx + t;
        const uint32_t a_base = smb + t * STAGE_BYTES;
        const __half* Ag = g_xg + (size_t)(by * BM) * C + f * BK;
        #pragma unroll
        for (int i = 0; i < 4; i++) {
            int id = tid + i * 256;
            int r = id >> 3, c = id & 7;
            cp_async16(a_base + r * 128 + ((c ^ (r & 7)) << 4), Ag + (size_t)r * C + c * 8);
        }
    }
    asm volatile("cp.async.commit_group;" ::: "memory");
    asm volatile("cp.async.wait_group 0;" ::: "memory");
    __syncthreads();

    // out_g = acc/3 + xg  (fp32 float2 stores: 4 lanes x 8B = full 32B sector)
    const int qid = lane >> 2, tq = lane & 3;
    #pragma unroll
    for (int mt = 0; mt < 4; mt++) {
        const int rloc0 = wm * 64 + mt * 16 + qid;      // local rows rloc0, rloc0+8
        #pragma unroll
        for (int nt = 0; nt < 4; nt++) {
            const int c   = wn * 32 + nt * 8 + 2 * tq;  // local col (0..127)
            const int t   = c >> 6;                     // which reloaded k-tile
            const int kc  = c & 63;                     // col within tile
            const int chv = kc >> 3;                    // 16B chunk index
            const int wb  = (kc & 7) * 2;               // byte offset in chunk
            #pragma unroll
            for (int h = 0; h < 2; h++) {               // rows rloc0 / rloc0+8
                const int rl = rloc0 + h * 8;
                const char* p = smem + t * STAGE_BYTES + rl * 128
                              + ((chv ^ (rl & 7)) << 4) + wb;
                float2 xv = __half22float2(*reinterpret_cast<const __half2*>(p));
                float2 o;
                o.x = fmaf(acc[mt][nt][2 * h],     RAND_SCALE, xv.x);
                o.y = fmaf(acc[mt][nt][2 * h + 1], RAND_SCALE, xv.y);
                *reinterpret_cast<float2*>(
                    g_og + (size_t)(by * BM + rl) * C + bx * BN + c) = o;
            }
        }
    }
}

// ---------------------------------------------------------------------------
// Launch 3: pure permutation.  out[r][a(i)] = out_g[r][i]
// 8 rows per 512-thread block; smem staging; 128 MB total traffic.
// ---------------------------------------------------------------------------
__global__ void __launch_bounds__(512)
permute_kernel(const int* __restrict__ perm,
               const int* __restrict__ randint,
               float*     __restrict__ out) {
    __shared__ float so[8][C];
    const int r0 = blockIdx.x * 8;
    const unsigned mult = ((unsigned)randint[0] * 6u) & 1023u;
    const int tid = threadIdx.x;

    // Phase 1: coalesced float4 read of out_g, scattered store into smem
    #pragma unroll
    for (int i = 0; i < 4; i++) {
        int id = tid + i * 512;                  // 0..2047 float4 chunks
        int rr = id >> 8, j = (id & 255) * 4;
        unsigned m = (mult * (unsigned)(r0 + rr) + 1u) & 1023u;
        float4 v = *reinterpret_cast<const float4*>(g_og + (size_t)(r0 + rr) * C + j);
        so[rr][((unsigned)perm[j]     * m) & 1023u] = v.x;
        so[rr][((unsigned)perm[j + 1] * m) & 1023u] = v.y;
        so[rr][((unsigned)perm[j + 2] * m) & 1023u] = v.z;
        so[rr][((unsigned)perm[j + 3] * m) & 1023u] = v.w;
    }
    __syncthreads();

    // Phase 2: coalesced float4 write of out
    #pragma unroll
    for (int i = 0; i < 4; i++) {
        int id = tid + i * 512;
        int rr = id >> 8, j = (id & 255) * 4;
        *reinterpret_cast<float4*>(out + (size_t)(r0 + rr) * C + j) =
            *reinterpret_cast<const float4*>(&so[rr][j]);
    }
}

// ---------------------------------------------------------------------------
extern "C" void kernel_launch(void* const* d_in, const int* in_sizes, int n_in,
                              void* d_out, int out_size) {
    const float* x       = (const float*)d_in[0];
    const float* U       = (const float*)d_in[1];
    const int*   perm    = (const int*)d_in[2];
    const int*   randint = (const int*)d_in[3];
    float*       out     = (float*)d_out;

    static bool attr_done = false;
    if (!attr_done) {
        cudaFuncSetAttribute(gemm_kernel,
                             cudaFuncAttributeMaxDynamicSharedMemorySize, GSMEM);
        attr_done = true;
    }

    gather_uconv_kernel<<<GATHER_BLOCKS + UCONV_BLOCKS, 512>>>(x, U, perm, randint);
    gemm_kernel<<<dim3(C / BN, M / BM), 256, GSMEM>>>();
    permute_kernel<<<M / 8, 512>>>(perm, randint, out);
}